// round 16
// baseline (speedup 1.0000x reference)
#include <cuda_runtime.h>
#include <cuda_fp16.h>
#include <stdint.h>

#define BB 64
#define CC 3
#define JJ 11
#define TT 512
#define CO 128
#define NPTS (BB*JJ*TT)      /* 360448 = 2816*128 */
#define SIGC 84
#define K1A 168
#define K2A 256
#define NT 128
#define GRIDG (NPTS/NT)      /* 2816 */
#define KS 64

// ---------------- static scratch ----------------
__device__ __half g_UVh[(size_t)K2A * NPTS];  // rows 0..127 = U, 128..255 = V (fp16)
__device__ __half g_Fh[(size_t)CO * NPTS];    // fus pre-BN (fp16)
__device__ uint4 g_Aps[6*512];                // fp16 A frag images ([kc32] x 512 slots)
__device__ uint4 g_Afus[8*512];
__device__ float g_pU[GRIDG*CO],  g_pUQ[GRIDG*CO];
__device__ float g_pV[GRIDG*CO],  g_pVQ[GRIDG*CO];
__device__ float g_pF[GRIDG*CO],  g_pFQ[GRIDG*CO];
__device__ float g_sc1[K2A], g_bi1[K2A];
__device__ float g_sc2[CO],  g_bi2[CO];

// ---------------- PTX helpers ----------------
__device__ __forceinline__ uint32_t smem_u32(const void* p) {
    uint32_t a;
    asm("{ .reg .u64 t; cvta.to.shared.u64 t, %1; cvt.u32.u64 %0, t; }" : "=r"(a) : "l"(p));
    return a;
}
__device__ __forceinline__ void ldsm_x2_t(uint32_t (&r)[2], uint32_t addr) {
    asm volatile("ldmatrix.sync.aligned.m8n8.x2.trans.shared.b16 {%0,%1}, [%2];"
        : "=r"(r[0]), "=r"(r[1]) : "r"(addr));
}
__device__ __forceinline__ void mma_f16(float (&d)[4], const uint4& a,
                                        uint32_t b0, uint32_t b1) {
    asm volatile("mma.sync.aligned.m16n8k16.row.col.f32.f16.f16.f32 "
        "{%0,%1,%2,%3}, {%4,%5,%6,%7}, {%8,%9}, {%0,%1,%2,%3};"
        : "+f"(d[0]), "+f"(d[1]), "+f"(d[2]), "+f"(d[3])
        : "r"(a.x), "r"(a.y), "r"(a.z), "r"(a.w), "r"(b0), "r"(b1));
}
__device__ __forceinline__ void cp16(uint32_t dst, const void* src, uint32_t sz) {
    asm volatile("cp.async.cg.shared.global [%0], [%1], 16, %2;"
        :: "r"(dst), "l"(src), "r"(sz));
}
#define CP_COMMIT() asm volatile("cp.async.commit_group;")
#define CP_WAIT0()  asm volatile("cp.async.wait_group 0;")
#define CP_WAIT1()  asm volatile("cp.async.wait_group 1;")

__device__ __forceinline__ uint32_t packh2(float a, float b) {
    __half2 h = __floats2half2_rn(a, b);
    return *(uint32_t*)&h;
}

// ---- SMEM layouts ----
#define PS_B    0
#define PS_A    52224
#define SMEM_PS 101376
#define OFF_A(s)   ((s)*16384)
#define OFF_B(s)   (32768 + (s)*17408)
#define OFF_RAW(s) (67584 + (s)*16384)
#define OFF_SC 100352
#define OFF_BI 101376
#define SMEM_FUS 102400

// ---------------- depth-3 signature Chen step (c = 4) ----------------
__device__ __forceinline__ void sig_step(float S1[4], float S2[16], float S3[64],
                                         const float d[4]) {
    float dd[16];
#pragma unroll
    for (int i = 0; i < 4; i++)
#pragma unroll
        for (int j = 0; j < 4; j++) dd[i*4+j] = d[i]*d[j];
    float a[4];
#pragma unroll
    for (int i = 0; i < 4; i++) a[i] = 0.5f*S1[i] + d[i]*(1.0f/6.0f);
#pragma unroll
    for (int i = 0; i < 4; i++)
#pragma unroll
        for (int j = 0; j < 4; j++)
#pragma unroll
            for (int k = 0; k < 4; k++)
                S3[i*16+j*4+k] += S2[i*4+j]*d[k] + a[i]*dd[j*4+k];
#pragma unroll
    for (int i = 0; i < 4; i++)
#pragma unroll
        for (int j = 0; j < 4; j++)
            S2[i*4+j] += S1[i]*d[j] + 0.5f*dd[i*4+j];
#pragma unroll
    for (int i = 0; i < 4; i++) S1[i] += d[i];
}

// ---------------- prep: fp16 A fragment images (m16n8k16 layout, per kc32) ----------------
__global__ void k_prep(const float* __restrict__ psw, const float* __restrict__ fusw) {
    int which = blockIdx.x;
    const float* W = which ? fusw : psw;
    int K = which ? K2A : K1A;
    int nslot = which ? 8*512 : 6*512;
    uint4* A = which ? g_Afus : g_Aps;
    for (int s = threadIdx.x; s < nslot; s += blockDim.x) {
        int lane = s & 31, ks = (s >> 5) & 1, g = (s >> 6) & 7, kc = s >> 9;
        int r = g*16 + (lane >> 2);
        int kb = kc*32 + ks*16 + 2*(lane & 3);
        float a00 = (kb   < K) ? W[r*K + kb]       : 0.f;
        float a01 = (kb+1 < K) ? W[r*K + kb+1]     : 0.f;
        float a10 = (kb   < K) ? W[(r+8)*K + kb]   : 0.f;
        float a11 = (kb+1 < K) ? W[(r+8)*K + kb+1] : 0.f;
        float a20 = (kb+8 < K) ? W[r*K + kb+8]     : 0.f;
        float a21 = (kb+9 < K) ? W[r*K + kb+9]     : 0.f;
        float a30 = (kb+8 < K) ? W[(r+8)*K + kb+8] : 0.f;
        float a31 = (kb+9 < K) ? W[(r+8)*K + kb+9] : 0.f;
        A[s] = make_uint4(packh2(a00, a01), packh2(a10, a11),
                          packh2(a20, a21), packh2(a30, a31));
    }
}

// ---------------- fused signature + raw conv + ps GEMM ----------------
__global__ void __launch_bounds__(256, 2) k_sigps(
        const float* __restrict__ x, const int* __restrict__ path,
        const float* __restrict__ bias,
        const float* __restrict__ raww, const float* __restrict__ rawb) {
    extern __shared__ char smc[];
    __shared__ float sS[CO], sQ[CO];
    uint32_t sb = smem_u32(smc);
    int tid = threadIdx.x;
    int warp = tid >> 5, lane = tid & 31;
    int wm = (warp >> 2) * 64;
    int wn = (warp & 3) * 32;
    int gbase = (warp >> 2) * 4;
    int lq = lane >> 2, lr = lane & 3;
    int p0 = blockIdx.x * NT;

    // prefetch ALL A chunks (48KB) in one group
#pragma unroll
    for (int i = 0; i < 12; i++) {
        int m = tid + i*256;
        cp16(sb + PS_A + m*16, g_Aps + m, 16);
    }
    CP_COMMIT();

    if (tid < CO) { sS[tid] = 0.f; sQ[tid] = 0.f; }
    // zero padded B rows 168..191
    for (int i = tid; i < 24*136; i += 256) {
        int row = 168 + i/136, col = i % 136;
        *(__half*)(smc + PS_B + row*272 + col*2) = __float2half_rn(0.f);
    }

    // ---- phase 1: signatures -> B SMEM column pp ----
    {
        int pp = tid & 127;
        int which = tid >> 7;          // 0 = spatial, 1 = temporal
        int p = p0 + pp;
        int t  = p & (TT - 1);
        int bj = p >> 9;
        int j  = bj % JJ;
        int b  = bj / JJ;
        const float* xb = x + (size_t)b * CC * JJ * TT;

        float S1[4], S2[16], S3[64];
        float prev[3], cur[3], d[4];
#pragma unroll
        for (int i = 0; i < 4; i++)  S1[i] = 0.f;
#pragma unroll
        for (int i = 0; i < 16; i++) S2[i] = 0.f;
#pragma unroll
        for (int i = 0; i < 64; i++) S3[i] = 0.f;

        if (which == 0) {
            int j0 = path[j*3+0], j1 = path[j*3+1], j2 = path[j*3+2];
#pragma unroll
            for (int c = 0; c < 3; c++) prev[c] = xb[(c*JJ + j0)*TT + t];
            d[0] = 0.f; d[1] = prev[0]; d[2] = prev[1]; d[3] = prev[2];
            sig_step(S1, S2, S3, d);
#pragma unroll
            for (int c = 0; c < 3; c++) cur[c] = xb[(c*JJ + j1)*TT + t];
            d[0] = 0.5f;
#pragma unroll
            for (int c = 0; c < 3; c++) { d[c+1] = cur[c] - prev[c]; prev[c] = cur[c]; }
            sig_step(S1, S2, S3, d);
#pragma unroll
            for (int c = 0; c < 3; c++) cur[c] = xb[(c*JJ + j2)*TT + t];
            d[0] = 0.5f;
#pragma unroll
            for (int c = 0; c < 3; c++) d[c+1] = cur[c] - prev[c];
            sig_step(S1, S2, S3, d);
        } else {
#pragma unroll
            for (int l = 0; l < 7; l++) {
                int tc = t + l - 3;
                tc = tc < 0 ? 0 : (tc > TT-1 ? TT-1 : tc);
#pragma unroll
                for (int c = 0; c < 3; c++) cur[c] = xb[(c*JJ + j)*TT + tc];
                if (l == 0) {
                    d[0] = 0.f;
#pragma unroll
                    for (int c = 0; c < 3; c++) d[c+1] = cur[c];
                } else {
                    d[0] = 1.0f/6.0f;
#pragma unroll
                    for (int c = 0; c < 3; c++) d[c+1] = cur[c] - prev[c];
                }
#pragma unroll
                for (int c = 0; c < 3; c++) prev[c] = cur[c];
                sig_step(S1, S2, S3, d);
            }
        }
        char* B = smc + PS_B;
        int rowbase = which * SIGC;
#pragma unroll
        for (int i = 0; i < 4; i++)
            *(__half*)(B + (rowbase + i)*272 + pp*2) = __float2half_rn(S1[i]);
#pragma unroll
        for (int i = 0; i < 16; i++)
            *(__half*)(B + (rowbase + 4 + i)*272 + pp*2) = __float2half_rn(S2[i]);
#pragma unroll
        for (int i = 0; i < 64; i++)
            *(__half*)(B + (rowbase + 20 + i)*272 + pp*2) = __float2half_rn(S3[i]);
    }

    // ---- phase 1b: raw 1x3 conv -> U fp16 + BN partials (indep of SMEM B) ----
    {
        int bj = p0 >> 9;
        int t0 = p0 & (TT - 1);
        int b = bj / JJ, j = bj % JJ;
        int tl = lane << 2;                 // 4 consecutive points per lane
        float xv[3][6];
#pragma unroll
        for (int c = 0; c < 3; c++) {
            const float* xr = x + ((size_t)(b*CC + c)*JJ + j)*TT;
#pragma unroll
            for (int u = 0; u < 6; u++) {
                int t = t0 + tl - 1 + u;
                xv[c][u] = (t >= 0 && t < TT) ? xr[t] : 0.f;
            }
        }
#pragma unroll 1
        for (int oi = 0; oi < 16; oi++) {
            int o = warp*16 + oi;
            float wr[9];
#pragma unroll
            for (int i = 0; i < 9; i++) wr[i] = raww[o*9 + i];
            float bo = rawb[o];
            float s = 0.f, q = 0.f;
            __half hv[4];
#pragma unroll
            for (int i = 0; i < 4; i++) {
                float a = bo;
#pragma unroll
                for (int c = 0; c < 3; c++)
#pragma unroll
                    for (int kw = 0; kw < 3; kw++)
                        a = fmaf(xv[c][i + kw], wr[c*3 + kw], a);
                hv[i] = __float2half_rn(a);
                s += a; q += a*a;
            }
            *(uint2*)&g_UVh[(size_t)o*NPTS + p0 + tl] = *(uint2*)hv;
#pragma unroll
            for (int d = 16; d; d >>= 1) {
                s += __shfl_xor_sync(0xffffffffu, s, d);
                q += __shfl_xor_sync(0xffffffffu, q, d);
            }
            if (lane == 0) { g_pU[blockIdx.x*CO + o] = s; g_pUQ[blockIdx.x*CO + o] = q; }
        }
    }

    CP_WAIT0();
    __syncthreads();          // B complete + A visible

    // ---- phase 2: MMA, 3 chunks of K=64, no in-loop barriers ----
    float acc[4][4][4];
#pragma unroll
    for (int i = 0; i < 4; i++)
#pragma unroll
        for (int j = 0; j < 4; j++)
#pragma unroll
            for (int r = 0; r < 4; r++) acc[i][j][r] = 0.f;

#pragma unroll 1
    for (int c = 0; c < 3; c++) {
        const char* Ac = smc + PS_A + c*16384;
#pragma unroll
        for (int ks = 0; ks < 4; ks++) {
            const char* Ak = Ac + (ks >> 1)*8192;
            uint4 af[4];
#pragma unroll
            for (int i = 0; i < 4; i++)
                af[i] = *(const uint4*)(Ak + (gbase + i)*1024 + (ks & 1)*512 + lane*16);
#pragma unroll
            for (int j = 0; j < 4; j++) {
                uint32_t b[2];
                uint32_t boff = (uint32_t)((c*64 + ks*16 + (lane & 15))*272 + (wn + j*8)*2);
                ldsm_x2_t(b, sb + PS_B + boff);
#pragma unroll
                for (int i = 0; i < 4; i++)
                    mma_f16(acc[i][j], af[i], b[0], b[1]);
            }
        }
    }

    // ---- epilogue: bias, store V fp16 channel-major, fused BN partials ----
    __half* Out = g_UVh + (size_t)CO*NPTS;
#pragma unroll
    for (int i = 0; i < 4; i++) {
        int c0 = wm + i*16 + lq;
        int c1 = c0 + 8;
        float b0 = bias[c0], b1 = bias[c1];
        float s0 = 0.f, q0 = 0.f, s1 = 0.f, q1 = 0.f;
#pragma unroll
        for (int j = 0; j < 4; j++) {
            float v00 = acc[i][j][0] + b0, v01 = acc[i][j][1] + b0;
            float v10 = acc[i][j][2] + b1, v11 = acc[i][j][3] + b1;
            int p = p0 + wn + j*8 + (lr << 1);
            *(__half2*)&Out[(size_t)c0*NPTS + p] = __floats2half2_rn(v00, v01);
            *(__half2*)&Out[(size_t)c1*NPTS + p] = __floats2half2_rn(v10, v11);
            s0 += v00 + v01; q0 += v00*v00 + v01*v01;
            s1 += v10 + v11; q1 += v10*v10 + v11*v11;
        }
#pragma unroll
        for (int d = 1; d < 4; d <<= 1) {
            s0 += __shfl_xor_sync(0xffffffffu, s0, d);
            q0 += __shfl_xor_sync(0xffffffffu, q0, d);
            s1 += __shfl_xor_sync(0xffffffffu, s1, d);
            q1 += __shfl_xor_sync(0xffffffffu, q1, d);
        }
        if (lr == 0) {
            atomicAdd(&sS[c0], s0); atomicAdd(&sQ[c0], q0);
            atomicAdd(&sS[c1], s1); atomicAdd(&sQ[c1], q1);
        }
    }
    __syncthreads();
    if (tid < CO) {
        g_pV[blockIdx.x*CO + tid]  = sS[tid];
        g_pVQ[blockIdx.x*CO + tid] = sQ[tid];
    }
}

// ---------------- fus GEMM building blocks (KS=64) ----------------
__device__ __forceinline__ void issueAf(int c, int tid, uint32_t sb) {
#pragma unroll
    for (int i = 0; i < 4; i++) {
        int m = tid + i*256;
        cp16(sb + OFF_A(c & 1) + m*16, g_Afus + c*1024 + m, 16);
    }
}
__device__ __forceinline__ void issueRaw(int c, int tid, uint32_t sb, int p0) {
#pragma unroll
    for (int i = 0; i < 4; i++) {
        int m = tid + i*256;
        int kl = m >> 4;
        const __half* src = g_UVh + (size_t)(c*KS + kl)*NPTS + p0 + (m & 15)*8;
        cp16(sb + OFF_RAW(c & 1) + m*16, src, 16);
    }
}
__device__ __forceinline__ void convF(int cc, int tid, char* smc,
        const float* s_sc, const float* s_bi) {
    const char* raw = smc + OFF_RAW(cc & 1);
    char* B = smc + OFF_B(cc & 1);
#pragma unroll
    for (int i = 0; i < 4; i++) {
        int m = tid + i*256;
        int kl = m >> 4, seg = m & 15;
        uint4 v = *(const uint4*)(raw + m*16);
        int kg = cc*KS + kl;
        float sc = s_sc[kg], bi = s_bi[kg];
        uint4 o;
        uint32_t* vp = (uint32_t*)&v;
        uint32_t* op = (uint32_t*)&o;
#pragma unroll
        for (int q = 0; q < 4; q++) {
            float2 f = __half22float2(*(__half2*)&vp[q]);
            f.x = fmaxf(fmaf(f.x, sc, bi), 0.f);
            f.y = fmaxf(fmaf(f.y, sc, bi), 0.f);
            op[q] = packh2(f.x, f.y);
        }
        *(uint4*)(B + kl*272 + seg*16) = o;
    }
}

// ---------------- pipelined fus GEMM ----------------
__global__ void __launch_bounds__(256, 2) k_fus(const float* __restrict__ bias) {
    extern __shared__ char smc[];
    __shared__ float sS[CO], sQ[CO];
    uint32_t sb = smem_u32(smc);
    float* s_sc = (float*)(smc + OFF_SC);
    float* s_bi = (float*)(smc + OFF_BI);

    int tid = threadIdx.x;
    int warp = tid >> 5, lane = tid & 31;
    int wm = (warp >> 2) * 64;
    int wn = (warp & 3) * 32;
    int gbase = (warp >> 2) * 4;
    int lq = lane >> 2, lr = lane & 3;
    int p0 = blockIdx.x * NT;

    for (int i = tid; i < K2A; i += 256) { s_sc[i] = g_sc1[i]; s_bi[i] = g_bi1[i]; }
    if (tid < CO) { sS[tid] = 0.f; sQ[tid] = 0.f; }
    __syncthreads();

    float acc[4][4][4];
#pragma unroll
    for (int i = 0; i < 4; i++)
#pragma unroll
        for (int j = 0; j < 4; j++)
#pragma unroll
            for (int r = 0; r < 4; r++) acc[i][j][r] = 0.f;

    issueAf(0, tid, sb); issueRaw(0, tid, sb, p0); CP_COMMIT();
    issueAf(1, tid, sb); issueRaw(1, tid, sb, p0); CP_COMMIT();
    CP_WAIT1();
    convF(0, tid, smc, s_sc, s_bi);
    __syncthreads();

    for (int c = 0; c < 4; c++) {
        int s = c & 1;
        const char* As = smc + OFF_A(s);
#pragma unroll
        for (int ks = 0; ks < 4; ks++) {
            const char* Ak = As + (ks >> 1)*8192;
            uint4 af[4];
#pragma unroll
            for (int i = 0; i < 4; i++)
                af[i] = *(const uint4*)(Ak + (gbase + i)*1024 + (ks & 1)*512 + lane*16);
#pragma unroll
            for (int j = 0; j < 4; j++) {
                uint32_t b[2];
                uint32_t boff = (uint32_t)((ks*16 + (lane & 15))*272 + (wn + j*8)*2);
                ldsm_x2_t(b, sb + OFF_B(s) + boff);
#pragma unroll
                for (int i = 0; i < 4; i++)
                    mma_f16(acc[i][j], af[i], b[0], b[1]);
            }
        }
        __syncthreads();
        if (c + 2 < 4) { issueAf(c+2, tid, sb); issueRaw(c+2, tid, sb, p0); }
        CP_COMMIT();
        CP_WAIT1();
        if (c + 1 < 4) convF(c+1, tid, smc, s_sc, s_bi);
        __syncthreads();
    }

    // ---- epilogue ----
#pragma unroll
    for (int i = 0; i < 4; i++) {
        int c0 = wm + i*16 + lq;
        int c1 = c0 + 8;
        float b0 = bias[c0], b1 = bias[c1];
        float s0 = 0.f, q0 = 0.f, s1 = 0.f, q1 = 0.f;
#pragma unroll
        for (int j = 0; j < 4; j++) {
            float v00 = acc[i][j][0] + b0, v01 = acc[i][j][1] + b0;
            float v10 = acc[i][j][2] + b1, v11 = acc[i][j][3] + b1;
            int p = p0 + wn + j*8 + (lr << 1);
            *(__half2*)&g_Fh[(size_t)c0*NPTS + p] = __floats2half2_rn(v00, v01);
            *(__half2*)&g_Fh[(size_t)c1*NPTS + p] = __floats2half2_rn(v10, v11);
            s0 += v00 + v01; q0 += v00*v00 + v01*v01;
            s1 += v10 + v11; q1 += v10*v10 + v11*v11;
        }
#pragma unroll
        for (int d = 1; d < 4; d <<= 1) {
            s0 += __shfl_xor_sync(0xffffffffu, s0, d);
            q0 += __shfl_xor_sync(0xffffffffu, q0, d);
            s1 += __shfl_xor_sync(0xffffffffu, s1, d);
            q1 += __shfl_xor_sync(0xffffffffu, q1, d);
        }
        if (lr == 0) {
            atomicAdd(&sS[c0], s0); atomicAdd(&sQ[c0], q0);
            atomicAdd(&sS[c1], s1); atomicAdd(&sQ[c1], q1);
        }
    }
    __syncthreads();
    if (tid < CO) {
        g_pF[blockIdx.x*CO + tid]  = sS[tid];
        g_pFQ[blockIdx.x*CO + tid] = sQ[tid];
    }
}

// ---------------- finalize BN affines ----------------
__global__ void k_fin1(const float* __restrict__ rg, const float* __restrict__ rb,
                       const float* __restrict__ pg, const float* __restrict__ pb) {
    int c = blockIdx.x;   // 0..255
    float s = 0.f, q = 0.f;
    if (c < CO) {
        for (int i = threadIdx.x; i < GRIDG; i += 128) { s += g_pU[i*CO + c]; q += g_pUQ[i*CO + c]; }
    } else {
        int cc = c - CO;
        for (int i = threadIdx.x; i < GRIDG; i += 128) { s += g_pV[i*CO + cc]; q += g_pVQ[i*CO + cc]; }
    }
    __shared__ float sh[256];
    sh[threadIdx.x] = s; sh[128 + threadIdx.x] = q;
    __syncthreads();
    for (int st = 64; st; st >>= 1) {
        if (threadIdx.x < st) {
            sh[threadIdx.x]       += sh[threadIdx.x + st];
            sh[128 + threadIdx.x] += sh[128 + threadIdx.x + st];
        }
        __syncthreads();
    }
    if (threadIdx.x == 0) {
        float mean = sh[0] / (float)NPTS;
        float var  = sh[128] / (float)NPTS - mean*mean;
        float rstd = rsqrtf(var + 1e-5f);
        float g  = (c < CO) ? rg[c] : pg[c - CO];
        float be = (c < CO) ? rb[c] : pb[c - CO];
        g_sc1[c] = rstd * g;
        g_bi1[c] = be - mean * rstd * g;
    }
}

__global__ void k_fin2(const float* __restrict__ fg, const float* __restrict__ fb) {
    int c = blockIdx.x;   // 0..127
    float s = 0.f, q = 0.f;
    for (int i = threadIdx.x; i < GRIDG; i += 128) { s += g_pF[i*CO + c]; q += g_pFQ[i*CO + c]; }
    __shared__ float sh[256];
    sh[threadIdx.x] = s; sh[128 + threadIdx.x] = q;
    __syncthreads();
    for (int st = 64; st; st >>= 1) {
        if (threadIdx.x < st) {
            sh[threadIdx.x]       += sh[threadIdx.x + st];
            sh[128 + threadIdx.x] += sh[128 + threadIdx.x + st];
        }
        __syncthreads();
    }
    if (threadIdx.x == 0) {
        float mean = sh[0] / (float)NPTS;
        float var  = sh[128] / (float)NPTS - mean*mean;
        float rstd = rsqrtf(var + 1e-5f);
        g_sc2[c] = rstd * fg[c];
        g_bi2[c] = fb[c] - mean * rstd * fg[c];
    }
}

// ---------------- final affine + relu + reshape (8 fp16 per thread) ----------------
__global__ void k_out(float* __restrict__ out) {
    int e8 = blockIdx.x * 256 + threadIdx.x;
    int idx = e8 << 3;
    int o = idx / NPTS;
    int p = idx - o * NPTS;
    int t  = p & (TT - 1);
    int bj = p >> 9;
    int j  = bj % JJ;
    int b  = bj / JJ;
    uint4 v = *(const uint4*)&g_Fh[idx];
    float sc = g_sc2[o], bi = g_bi2[o];
    const uint32_t* vp = (const uint32_t*)&v;
    float r[8];
#pragma unroll
    for (int q = 0; q < 4; q++) {
        float2 f = __half22float2(*(const __half2*)&vp[q]);
        r[q*2+0] = fmaxf(fmaf(f.x, sc, bi), 0.f);
        r[q*2+1] = fmaxf(fmaf(f.y, sc, bi), 0.f);
    }
    float* dst = &out[((b*CO + o)*JJ + j)*TT + t];
    *(float4*)dst       = make_float4(r[0], r[1], r[2], r[3]);
    *(float4*)(dst + 4) = make_float4(r[4], r[5], r[6], r[7]);
}

// ---------------- launcher ----------------
extern "C" void kernel_launch(void* const* d_in, const int* in_sizes, int n_in,
                              void* d_out, int out_size) {
    const float* x      = (const float*)d_in[0];
    const int*   path   = (const int*)  d_in[1];
    const float* raw_w  = (const float*)d_in[2];
    const float* raw_b  = (const float*)d_in[3];
    const float* raw_g  = (const float*)d_in[4];
    const float* raw_be = (const float*)d_in[5];
    const float* ps_w   = (const float*)d_in[6];
    const float* ps_b   = (const float*)d_in[7];
    const float* ps_g   = (const float*)d_in[8];
    const float* ps_be  = (const float*)d_in[9];
    const float* fus_w  = (const float*)d_in[10];
    const float* fus_b  = (const float*)d_in[11];
    const float* fus_g  = (const float*)d_in[12];
    const float* fus_be = (const float*)d_in[13];
    float* out = (float*)d_out;

    cudaFuncSetAttribute(k_sigps, cudaFuncAttributeMaxDynamicSharedMemorySize, SMEM_PS);
    cudaFuncSetAttribute(k_fus,   cudaFuncAttributeMaxDynamicSharedMemorySize, SMEM_FUS);

    k_prep<<<2, 256>>>(ps_w, fus_w);
    k_sigps<<<GRIDG, 256, SMEM_PS>>>(x, path, ps_b, raw_w, raw_b);
    k_fin1<<<2*CO, 128>>>(raw_g, raw_be, ps_g, ps_be);
    k_fus<<<GRIDG, 256, SMEM_FUS>>>(fus_b);
    k_fin2<<<CO, 128>>>(fus_g, fus_be);
    k_out<<<(CO*NPTS)/2048, 256>>>(out);
}